// round 15
// baseline (speedup 1.0000x reference)
#include <cuda_runtime.h>
#include <cuda_fp16.h>
#include <cstdint>

#define BB   16
#define CIN  512
#define COUT 512
#define HH   64
#define WW   64
#define SS   512

// ---------------- scratch (__device__ globals: allocation-free) ----------------
__device__ float g_smod[BB * CIN];      // s[b][i]
__device__ float g_demod[BB * COUT];    // demod[b][o]
__device__ float g_wsq[COUT * CIN];     // per-(o,i) 3x3 weight energy

// Winograd transformed weights U[p][oc][ic], p = xi*4+nu, fp16 (8MB)
__device__ __align__(16) unsigned short g_u[16 * COUT * CIN];
// Winograd transformed input V[b*16+p][tile][ic], fp16 (256MB)
__device__ __align__(16) unsigned short g_v[268435456 / 2];

// ---------------- baseline-ISA helpers ----------------
__device__ __forceinline__ void cp16(uint32_t dst, const void* src) {
    asm volatile("cp.async.cg.shared.global [%0], [%1], 16;" :: "r"(dst), "l"(src) : "memory");
}
__device__ __forceinline__ void cp_commit() { asm volatile("cp.async.commit_group;" ::: "memory"); }
template <int N> __device__ __forceinline__ void cp_wait() {
    asm volatile("cp.async.wait_group %0;" :: "n"(N) : "memory");
}
#define LDSM4(r, addr) \
    asm volatile("ldmatrix.sync.aligned.m8n8.x4.shared.b16 {%0,%1,%2,%3}, [%4];" \
                 : "=r"((r)[0]), "=r"((r)[1]), "=r"((r)[2]), "=r"((r)[3]) : "r"(addr))
#define MMA(c, a, b0v, b1v) \
    asm volatile("mma.sync.aligned.m16n8k16.row.col.f32.f16.f16.f32 " \
                 "{%0,%1,%2,%3}, {%4,%5,%6,%7}, {%8,%9}, {%0,%1,%2,%3};" \
                 : "+f"((c)[0]), "+f"((c)[1]), "+f"((c)[2]), "+f"((c)[3]) \
                 : "r"((a)[0]), "r"((a)[1]), "r"((a)[2]), "r"((a)[3]), "r"(b0v), "r"(b1v))

// ---------------- kernel 1: s = style @ mod_w^T + mod_b ----------------
__global__ void k_mod(const float* __restrict__ style, const float* __restrict__ mod_w,
                      const float* __restrict__ mod_b) {
    int wid  = (blockIdx.x * blockDim.x + threadIdx.x) >> 5;
    int lane = threadIdx.x & 31;
    if (wid >= BB * CIN) return;
    int b = wid >> 9, i = wid & 511;
    const float* st = style + b * SS;
    const float* mw = mod_w + (size_t)i * SS;
    float sum = 0.f;
    for (int l = lane; l < SS; l += 32) sum += st[l] * mw[l];
    #pragma unroll
    for (int o = 16; o > 0; o >>= 1) sum += __shfl_xor_sync(0xffffffffu, sum, o);
    if (lane == 0) g_smod[wid] = sum + mod_b[i];
}

// ---------------- kernel 2: wsq ----------------
__global__ void k_wsq(const float* __restrict__ weight) {
    int idx = blockIdx.x * blockDim.x + threadIdx.x;
    if (idx >= COUT * CIN) return;
    const float* w = weight + (size_t)idx * 9;
    float s = 0.f;
    #pragma unroll
    for (int t = 0; t < 9; ++t) s += w[t] * w[t];
    g_wsq[idx] = s;
}

// ---------------- kernel 3: demod ----------------
__global__ void k_demod() {
    int wid  = (blockIdx.x * blockDim.x + threadIdx.x) >> 5;
    int lane = threadIdx.x & 31;
    if (wid >= BB * COUT) return;
    int b = wid >> 9, o = wid & 511;
    const float* wsq = g_wsq + (size_t)o * CIN;
    const float* sm  = g_smod + b * CIN;
    float sum = 0.f;
    for (int i = lane; i < CIN; i += 32) { float s = sm[i]; sum += wsq[i] * s * s; }
    #pragma unroll
    for (int off = 16; off > 0; off >>= 1) sum += __shfl_xor_sync(0xffffffffu, sum, off);
    const float scale2 = 2.1701389e-4f;   // 1/(Cin*K*K)
    if (lane == 0) g_demod[wid] = rsqrtf(scale2 * sum + 1e-8f);
}

// ---------------- kernel 4: Winograd weight transform U = G (scale*w) G^T -----
__global__ void k_uprep(const float* __restrict__ weight) {
    int idx = blockIdx.x * 256 + threadIdx.x;       // oc*512 + ic
    if (idx >= COUT * CIN) return;
    const float* w = weight + (size_t)idx * 9;
    const float sc = 0.014731391f;                   // 1/sqrt(4608)
    float g0[3], g1[3], g2[3];
    #pragma unroll
    for (int j = 0; j < 3; ++j) { g0[j] = w[j] * sc; g1[j] = w[3 + j] * sc; g2[j] = w[6 + j] * sc; }
    float t[4][3];
    #pragma unroll
    for (int j = 0; j < 3; ++j) {
        t[0][j] = g0[j];
        t[1][j] = 0.5f * (g0[j] + g1[j] + g2[j]);
        t[2][j] = 0.5f * (g0[j] - g1[j] + g2[j]);
        t[3][j] = g2[j];
    }
    #pragma unroll
    for (int i = 0; i < 4; ++i) {
        float u0 = t[i][0];
        float u1 = 0.5f * (t[i][0] + t[i][1] + t[i][2]);
        float u2 = 0.5f * (t[i][0] - t[i][1] + t[i][2]);
        float u3 = t[i][2];
        g_u[(size_t)(i * 4 + 0) * (COUT * CIN) + idx] = __half_as_ushort(__float2half_rn(u0));
        g_u[(size_t)(i * 4 + 1) * (COUT * CIN) + idx] = __half_as_ushort(__float2half_rn(u1));
        g_u[(size_t)(i * 4 + 2) * (COUT * CIN) + idx] = __half_as_ushort(__float2half_rn(u2));
        g_u[(size_t)(i * 4 + 3) * (COUT * CIN) + idx] = __half_as_ushort(__float2half_rn(u3));
    }
}

// ---------------- kernel 5: Winograd input transform V = B^T (s*d) B ----------
__global__ void __launch_bounds__(256)
k_vprep(const float* __restrict__ input) {
    extern __shared__ float sm[];
    float* sx = sm;                                            // [row*66+col][ic]
    __half2* vs = (__half2*)((char*)sm + 67584);               // [p][tx][icp]
    const int ty = blockIdx.x, icb = blockIdx.y, b = blockIdx.z;
    const int tid = threadIdx.x;

    {
        int ic = tid & 63, row = tid >> 6;
        int icg = (icb << 6) + ic;
        float s = g_smod[b * CIN + icg];
        int gr = 2 * ty - 1 + row;
        float* dst = sx + (row * 66) * 64 + ic;
        if (gr >= 0 && gr < HH) {
            const float4* src = (const float4*)(input + ((size_t)(b * CIN + icg) * HH + gr) * WW);
            dst[0] = 0.f; dst[65 * 64] = 0.f;
            #pragma unroll
            for (int c4 = 0; c4 < 16; ++c4) {
                float4 v = src[c4];
                dst[(c4 * 4 + 1) * 64] = v.x * s;
                dst[(c4 * 4 + 2) * 64] = v.y * s;
                dst[(c4 * 4 + 3) * 64] = v.z * s;
                dst[(c4 * 4 + 4) * 64] = v.w * s;
            }
        } else {
            #pragma unroll
            for (int c = 0; c < 66; ++c) dst[c * 64] = 0.f;
        }
    }
    __syncthreads();

    {
        int icp = tid & 31, txg = tid >> 5;
        #pragma unroll
        for (int k = 0; k < 4; ++k) {
            int tx = txg + (k << 3);
            float dx[4][4], dy[4][4];
            #pragma unroll
            for (int r = 0; r < 4; ++r)
                #pragma unroll
                for (int c = 0; c < 4; ++c) {
                    float2 v = *(const float2*)(sx + ((r * 66) + (2 * tx + c)) * 64 + icp * 2);
                    dx[r][c] = v.x; dy[r][c] = v.y;
                }
            float txm[4][4], tym[4][4];
            #pragma unroll
            for (int j = 0; j < 4; ++j) {
                txm[0][j] = dx[0][j] - dx[2][j];  tym[0][j] = dy[0][j] - dy[2][j];
                txm[1][j] = dx[1][j] + dx[2][j];  tym[1][j] = dy[1][j] + dy[2][j];
                txm[2][j] = dx[2][j] - dx[1][j];  tym[2][j] = dy[2][j] - dy[1][j];
                txm[3][j] = dx[1][j] - dx[3][j];  tym[3][j] = dy[1][j] - dy[3][j];
            }
            #pragma unroll
            for (int i = 0; i < 4; ++i) {
                float vx0 = txm[i][0] - txm[i][2], vy0 = tym[i][0] - tym[i][2];
                float vx1 = txm[i][1] + txm[i][2], vy1 = tym[i][1] + tym[i][2];
                float vx2 = txm[i][2] - txm[i][1], vy2 = tym[i][2] - tym[i][1];
                float vx3 = txm[i][1] - txm[i][3], vy3 = tym[i][1] - tym[i][3];
                vs[((i * 4 + 0) * 32 + tx) * 32 + icp] = __floats2half2_rn(vx0, vy0);
                vs[((i * 4 + 1) * 32 + tx) * 32 + icp] = __floats2half2_rn(vx1, vy1);
                vs[((i * 4 + 2) * 32 + tx) * 32 + icp] = __floats2half2_rn(vx2, vy2);
                vs[((i * 4 + 3) * 32 + tx) * 32 + icp] = __floats2half2_rn(vx3, vy3);
            }
        }
    }
    __syncthreads();

    {
        const uint4* vsrc = (const uint4*)vs;
        #pragma unroll
        for (int k = 0; k < 16; ++k) {
            int j = tid + (k << 8);
            int p = j >> 8, rem = j & 255, tx = rem >> 3, ch = rem & 7;
            uint4 val = vsrc[(p * 32 + tx) * 8 + ch];
            *(uint4*)(g_v + (((size_t)(b * 16 + p) * 1024 + ty * 32 + tx) * 512 + (icb << 6) + ch * 8)) = val;
        }
    }
}

// ---------------- kernel 6: fused Winograd GEMM + output transform ------------
// CTA: 128 oc x 64 output-tiles. Loops p=0..15; per p a K=512 GEMM (8 k-iters),
// M_p stays in fp32 regs and is folded into persistent Y accumulators with the
// A^T coefficients. 128 pipelined iterations, 3-slot ring (24KB/slot = 72KB),
// single sync per iteration (R13 discipline). No M tensor, no ytrans kernel.
__global__ void __launch_bounds__(256, 1)
k_wino(float* __restrict__ out) {
    extern __shared__ char dsm[];
    const int tid = threadIdx.x, lane = tid & 31, wid = tid >> 5;
    const int wm = wid >> 2, wn = wid & 3;              // 2 m-warps x 4 n-warps
    const int b = blockIdx.z, ocb = blockIdx.y << 7, tb = blockIdx.x << 6;

    const uint32_t sb = (uint32_t)__cvta_generic_to_shared(dsm);

    uint32_t arow_off[4];
    #pragma unroll
    for (int mi = 0; mi < 4; ++mi)
        arow_off[mi] = (uint32_t)((wm * 64 + mi * 16 + (lane & 15)) * 128);
    const uint32_t brow_off = (uint32_t)((wn * 16 + ((lane >> 4) << 3) + (lane & 7)) * 128);
    const uint32_t swz = (uint32_t)(lane & 7);

    float y[4][2][4][4];        // [mi][nt][accv][pos]; pos: y00,y01,y10,y11
    #pragma unroll
    for (int mi = 0; mi < 4; ++mi)
        #pragma unroll
        for (int nt = 0; nt < 2; ++nt)
            #pragma unroll
            for (int v = 0; v < 4; ++v)
                #pragma unroll
                for (int q = 0; q < 4; ++q) y[mi][nt][v][q] = 0.f;

    float acc[4][2][4];
    #pragma unroll
    for (int mi = 0; mi < 4; ++mi)
        #pragma unroll
        for (int nt = 0; nt < 2; ++nt)
            #pragma unroll
            for (int q = 0; q < 4; ++q) acc[mi][nt][q] = 0.f;

    // slot layout: {U:16KB, V:8KB} per slot, 3 slots (24KB stride)
    auto issue = [&](int g) {
        const int p = g >> 3, icb = (g & 7) << 6;
        const uint32_t s0 = sb + (uint32_t)(g % 3) * 24576u;
        const unsigned short* ug = g_u + (size_t)p * (COUT * CIN);
        const unsigned short* vg = g_v + ((size_t)(b * 16 + p) * 1024 + tb) * 512;
        #pragma unroll
        for (int k2 = 0; k2 < 4; ++k2) {                 // U: 128 rows x 64 ic
            int q = tid + (k2 << 8);
            int row = q >> 3, cc = q & 7;
            uint32_t doff = (uint32_t)(row * 128 + (((uint32_t)cc ^ (uint32_t)(row & 7)) << 4));
            cp16(s0 + doff, ug + ((size_t)(ocb + row)) * 512 + icb + (cc << 3));
        }
        #pragma unroll
        for (int k2 = 0; k2 < 2; ++k2) {                 // V: 64 tile-rows x 64 ic
            int q = tid + (k2 << 8);
            int row = q >> 3, cc = q & 7;
            uint32_t doff = (uint32_t)(row * 128 + (((uint32_t)cc ^ (uint32_t)(row & 7)) << 4));
            cp16(s0 + 16384 + doff, vg + ((size_t)row) * 512 + icb + (cc << 3));
        }
        cp_commit();
    };

    issue(0);
    issue(1);
    for (int it = 0; it < 128; ++it) {
        if (it < 126)       { issue(it + 2); cp_wait<2>(); }
        else if (it == 126) { cp_wait<1>(); }
        else                { cp_wait<0>(); }
        __syncthreads();

        const uint32_t s0 = sb + (uint32_t)(it % 3) * 24576u;
        const uint32_t x0 = s0 + 16384u;
        #pragma unroll
        for (int ks = 0; ks < 4; ++ks) {
            const uint32_t ca = (((uint32_t)(2 * ks) + (uint32_t)(lane >> 4)) ^ swz) << 4;
            const uint32_t cb = (((uint32_t)(2 * ks) + (uint32_t)((lane >> 3) & 1)) ^ swz) << 4;
            uint32_t Ah[4][4], Bh[4];
            #pragma unroll
            for (int mi = 0; mi < 4; ++mi)
                LDSM4(Ah[mi], s0 + arow_off[mi] + ca);
            LDSM4(Bh, x0 + brow_off + cb);
            #pragma unroll
            for (int mi = 0; mi < 4; ++mi)
                #pragma unroll
                for (int nt = 0; nt < 2; ++nt)
                    MMA(acc[mi][nt], Ah[mi], Bh[nt * 2], Bh[nt * 2 + 1]);
        }

        if ((it & 7) == 7) {
            // fold M_p (in acc) into Y with A^T coefficients, then clear acc
            const int p = it >> 3, xi = p >> 2, nu = p & 3;
            const float a0x = (xi < 3) ? 1.f : 0.f;
            const float a1x = (xi == 0) ? 0.f : ((xi == 1) ? 1.f : -1.f);
            const float a0n = (nu < 3) ? 1.f : 0.f;
            const float a1n = (nu == 0) ? 0.f : ((nu == 1) ? 1.f : -1.f);
            const float c00 = a0x * a0n, c01 = a0x * a1n;
            const float c10 = a1x * a0n, c11 = a1x * a1n;
            #pragma unroll
            for (int mi = 0; mi < 4; ++mi)
                #pragma unroll
                for (int nt = 0; nt < 2; ++nt)
                    #pragma unroll
                    for (int v = 0; v < 4; ++v) {
                        const float m = acc[mi][nt][v];
                        y[mi][nt][v][0] += c00 * m;
                        y[mi][nt][v][1] += c01 * m;
                        y[mi][nt][v][2] += c10 * m;
                        y[mi][nt][v][3] += c11 * m;
                        acc[mi][nt][v] = 0.f;
                    }
        }
    }

    // -------- epilogue: demod scale + store (4 px per tile) --------
    #pragma unroll
    for (int mi = 0; mi < 4; ++mi) {
        const int oc0 = ocb + wm * 64 + mi * 16 + (lane >> 2), oc1 = oc0 + 8;
        const float d0 = g_demod[b * COUT + oc0];
        const float d1 = g_demod[b * COUT + oc1];
        #pragma unroll
        for (int nt = 0; nt < 2; ++nt) {
            const int tg = tb + wn * 16 + nt * 8 + ((lane & 3) << 1);   // even; tg+1 same tile-row
            const int tty = tg >> 5, ttx = tg & 31;
            // oc0: accv 0 (tile tg), accv 1 (tile tg+1)
            float* q0 = out + (((size_t)(b * COUT + oc0) * 64 + 2 * tty) * 64 + 2 * ttx);
            *(float4*)q0 = make_float4(y[mi][nt][0][0] * d0, y[mi][nt][0][1] * d0,
                                       y[mi][nt][1][0] * d0, y[mi][nt][1][1] * d0);
            *(float4*)(q0 + 64) = make_float4(y[mi][nt][0][2] * d0, y[mi][nt][0][3] * d0,
                                              y[mi][nt][1][2] * d0, y[mi][nt][1][3] * d0);
            // oc1: accv 2 (tile tg), accv 3 (tile tg+1)
            float* q1 = out + (((size_t)(b * COUT + oc1) * 64 + 2 * tty) * 64 + 2 * ttx);
            *(float4*)q1 = make_float4(y[mi][nt][2][0] * d1, y[mi][nt][2][1] * d1,
                                       y[mi][nt][3][0] * d1, y[mi][nt][3][1] * d1);
            *(float4*)(q1 + 64) = make_float4(y[mi][nt][2][2] * d1, y[mi][nt][2][3] * d1,
                                              y[mi][nt][3][2] * d1, y[mi][nt][3][3] * d1);
        }
    }
}

// ---------------- launch ----------------
extern "C" void kernel_launch(void* const* d_in, const int* in_sizes, int n_in,
                              void* d_out, int out_size) {
    const float* input  = (const float*)d_in[0];  // (16,512,64,64)
    const float* style  = (const float*)d_in[1];  // (16,512)
    const float* weight = (const float*)d_in[2];  // (512,512,3,3)
    const float* mod_w  = (const float*)d_in[3];  // (512,512)
    const float* mod_b  = (const float*)d_in[4];  // (512,)
    float* out = (float*)d_out;                   // (16,512,64,64)
    (void)in_sizes; (void)n_in; (void)out_size;

    k_mod   <<<1024, 256>>>(style, mod_w, mod_b);
    k_wsq   <<<1024, 256>>>(weight);
    k_demod <<<1024, 256>>>();
    k_uprep <<<1024, 256>>>(weight);

    cudaFuncSetAttribute(k_vprep, cudaFuncAttributeMaxDynamicSharedMemorySize, 133120);
    k_vprep<<<dim3(32, 8, 16), 256, 133120>>>(input);

    cudaFuncSetAttribute(k_wino, cudaFuncAttributeMaxDynamicSharedMemorySize, 73728);
    k_wino<<<dim3(16, 4, 16), 256, 73728>>>(out);
}